// round 13
// baseline (speedup 1.0000x reference)
#include <cuda_runtime.h>
#include <cuda_fp16.h>
#include <stdint.h>

#define B_    4
#define S_    4096
#define HID_  1024
#define NH_   16
#define M_    (B_*S_)      /* 16384 rows */
#define K_    1024
#define NEXT_ 1152         /* GEMM1 N: 1024 P + 32 gates + 16 forget + 80 pad */
#define NSEG_ 32
#define TSEG_ 128
#define CS_   16
#define OUT_OFF_ ((size_t)M_*HID_)

/* ------------------- device scratch (static, no allocs) ------------------- */
__device__ __half g_xh   [(size_t)M_*K_];
__device__ __half g_Bmat [(size_t)NEXT_*K_];
__device__ __half g_Wouth[(size_t)HID_*K_];
__device__ __half g_Pext [(size_t)M_*NEXT_];
__device__ float  g_psum[32][M_], g_psq[32][M_];   /* per-32col-slice LN partials */
__device__ float  g_s[32], g_c1[32], g_eig[16];
__device__ float  g_Gpart[8*32*1024];
__device__ float  g_Aseg[B_*NSEG_*HID_], g_Bseg[B_*NSEG_*HID_];
__device__ float  g_S0  [B_*NSEG_*HID_];           /* segment-entry state */
__device__ float  g_cumA[(size_t)M_*NH_];          /* per-row per-head running prod(a) */
__device__ __half g_h16 [(size_t)M_*HID_];

/* ============ prep_all: conv x -> fp16 | gemmG partials | s/c1/eig ============ */
#define NB_CONV_  (M_*K_/4/256)     /* 16384 */
#define NB_GEMMG_ 256               /* 32 gates x 8 k-slices */
__global__ void k_prep_all(const float* __restrict__ x,
                           const float* __restrict__ W_in,
                           const float* __restrict__ Wg,  const float* __restrict__ bg,
                           const float* __restrict__ gamma, const float* __restrict__ beta,
                           const float* __restrict__ eraw){
  const int bid = blockIdx.x, tid = threadIdx.x;
  if (bid < NB_CONV_){
    size_t i = (size_t)bid*256 + tid;
    float4 v = ((const float4*)x)[i];
    __half2* d = (__half2*)g_xh;
    d[2*i]   = __floats2half2_rn(v.x, v.y);
    d[2*i+1] = __floats2half2_rn(v.z, v.w);
    return;
  }
  int rem = bid - NB_CONV_;
  if (rem < NB_GEMMG_){
    __shared__ float wgg[128];
    const int g = rem & 31, ky = rem >> 5, k0 = ky*128;
    if (tid < 128) wgg[tid] = gamma[k0 + tid]*Wg[g*1024 + k0 + tid];
    __syncthreads();
    float acc[4] = {0.f,0.f,0.f,0.f};
    for (int k = 0; k < 128; k++){
      float w = wgg[k];
      const float* r = W_in + (size_t)(k0 + k)*1024 + tid;
#pragma unroll
      for (int j = 0; j < 4; j++) acc[j] = fmaf(w, r[j*256], acc[j]);
    }
#pragma unroll
    for (int j = 0; j < 4; j++) g_Gpart[(ky*32 + g)*1024 + tid + j*256] = acc[j];
    return;
  }
  int w = tid >> 5, lane = tid & 31;
  for (int g = w; g < 32; g += 8){
    float ss = 0.f, cc = 0.f;
    for (int k = lane; k < 1024; k += 32){
      float wv = Wg[g*1024 + k];
      ss += gamma[k]*wv;
      cc += beta[k]*wv;
    }
    for (int o = 16; o; o >>= 1){
      ss += __shfl_xor_sync(0xffffffffu, ss, o);
      cc += __shfl_xor_sync(0xffffffffu, cc, o);
    }
    if (lane == 0){ g_s[g] = ss; g_c1[g] = cc + bg[g]; }
  }
  if (tid < 16) g_eig[tid] = tanhf(eraw[tid]);
}

/* --- fill Bmat rows [W_in; G; Wf; 0] AND convert Wout (merged kernel) --- */
#define FILLB_BLKS_ (NEXT_*K_/256)          /* 4608 */
#define FILLW_BLKS_ (HID_*K_/256)           /* 4096 */
__global__ void k_fill_Bmat(const float* __restrict__ W_in, const float* __restrict__ Wf,
                            const float* __restrict__ Wout){
  int bid = blockIdx.x;
  if (bid < FILLB_BLKS_){
    int idx = bid*256 + threadIdx.x;
    int row = idx >> 10, col = idx & 1023;
    float v;
    if (row < 1024)       v = W_in[idx];
    else if (row < 1056){
      int g = row - 1024;
      v = 0.f;
#pragma unroll
      for (int ky = 0; ky < 8; ky++) v += g_Gpart[(ky*32 + g)*1024 + col];
    }
    else if (row < 1072)  v = Wf[(row-1056)*1024 + col];
    else                  v = 0.f;
    g_Bmat[idx] = __float2half(v);
  } else {
    int idx = (bid - FILLB_BLKS_)*256 + threadIdx.x;
    g_Wouth[idx] = __float2half(Wout[idx]);
  }
}

/* ------------------------------ fp16 GEMM (mma.sync) ------------------------------ */
__device__ __forceinline__ void ldm_x4(unsigned addr, unsigned &r0, unsigned &r1, unsigned &r2, unsigned &r3){
  asm volatile("ldmatrix.sync.aligned.m8n8.x4.shared.b16 {%0,%1,%2,%3}, [%4];"
               : "=r"(r0),"=r"(r1),"=r"(r2),"=r"(r3) : "r"(addr));
}
__device__ __forceinline__ void mma16816(float c[4], unsigned a0, unsigned a1, unsigned a2, unsigned a3,
                                         unsigned b0, unsigned b1){
  asm volatile("mma.sync.aligned.m16n8k16.row.col.f32.f16.f16.f32 "
               "{%0,%1,%2,%3},{%4,%5,%6,%7},{%8,%9},{%0,%1,%2,%3};"
               : "+f"(c[0]),"+f"(c[1]),"+f"(c[2]),"+f"(c[3])
               : "r"(a0),"r"(a1),"r"(a2),"r"(a3),"r"(b0),"r"(b1));
}

#define GASTAGE_ 32768
#define GBSTAGE_ 16384
#define GB_OFF_  (3*GASTAGE_)
#define GSM_TOTAL_ (3*GASTAGE_ + 3*GBSTAGE_)   /* 144 KB */
#define GEMM_GRID_ 152

template<int MODE>   /* 0: P_ext(fp16) = x_h @ Bmat^T   1: out(fp32) = h16 @ Wout^T */
__global__ void __launch_bounds__(512,1) k_gemm(float* __restrict__ Cout){
  constexpr int LDC = (MODE==0) ? NEXT_ : HID_;
  constexpr int NTN = (MODE==0) ? 9 : 8;
  constexpr int NT  = (M_/256)*NTN;
  const __half* __restrict__ A  = (MODE==0) ? g_xh   : g_h16;
  const __half* __restrict__ Bm = (MODE==0) ? g_Bmat : g_Wouth;

  extern __shared__ __align__(128) char smem[];
  const unsigned sbase = (unsigned)__cvta_generic_to_shared(smem);

  const int tid = threadIdx.x;
  const int lane = tid & 31, warp = tid >> 5;
  const int wm = (warp & 3)*64, wn = (warp >> 2)*32;
  const int unit = tid & 7;
  const int rb   = tid >> 3;

  for (int t = blockIdx.x; t < NT; t += GEMM_GRID_){
    const int m0 = (t / NTN)*256, n0 = (t % NTN)*128;

    __syncthreads();

    float acc[4][4][4];
#pragma unroll
    for (int i=0;i<4;i++)
#pragma unroll
      for (int j=0;j<4;j++)
#pragma unroll
        for (int k=0;k<4;k++) acc[i][j][k]=0.f;

    auto load_tiles = [&](int stage, int kt){
      const int kb = kt*64 + unit*8;
      const unsigned abase = sbase + stage*GASTAGE_;
      const unsigned bbase = sbase + GB_OFF_ + stage*GBSTAGE_;
#pragma unroll
      for (int i=0;i<4;i++){
        int r = rb + i*64;
        unsigned d = abase + r*128 + ((unit ^ (r&7))*16);
        asm volatile("cp.async.cg.shared.global [%0], [%1], 16;"
                     :: "r"(d), "l"(A + (size_t)(m0+r)*K_ + kb));
      }
#pragma unroll
      for (int i=0;i<2;i++){
        int r = rb + i*64;
        unsigned d = bbase + r*128 + ((unit ^ (r&7))*16);
        asm volatile("cp.async.cg.shared.global [%0], [%1], 16;"
                     :: "r"(d), "l"(Bm + (size_t)(n0+r)*K_ + kb));
      }
      asm volatile("cp.async.commit_group;");
    };

    load_tiles(0, 0);
    load_tiles(1, 1);
    const int NK = K_/64;
    for (int kt = 0; kt < NK; kt++){
      asm volatile("cp.async.wait_group 1;\n");
      __syncthreads();
      if (kt+2 < NK) load_tiles((kt+2)%3, kt+2);
      else           asm volatile("cp.async.commit_group;\n");
      const int stage = kt % 3;
      const unsigned abase = sbase + stage*GASTAGE_;
      const unsigned bbase = sbase + GB_OFF_ + stage*GBSTAGE_;
#pragma unroll
      for (int ks = 0; ks < 4; ks++){
        const int kc  = ks*16 + ((lane&16)?8:0);
        const int kcb = ks*16 + ((lane&8)?8:0);
        unsigned af[4][4];
#pragma unroll
        for (int mt=0; mt<4; mt++){
          int row = wm + mt*16 + (lane&15);
          ldm_x4(abase + row*128 + (((kc>>3) ^ (row&7))*16),
                 af[mt][0],af[mt][1],af[mt][2],af[mt][3]);
        }
        unsigned bf[4][2];
#pragma unroll
        for (int np=0; np<2; np++){
          int row = wn + np*16 + (lane&7) + ((lane&16)?8:0);
          unsigned t0,t1,t2,t3;
          ldm_x4(bbase + row*128 + (((kcb>>3) ^ (row&7))*16), t0,t1,t2,t3);
          bf[np*2][0]=t0; bf[np*2][1]=t1; bf[np*2+1][0]=t2; bf[np*2+1][1]=t3;
        }
#pragma unroll
        for (int mt=0; mt<4; mt++)
#pragma unroll
          for (int nt=0; nt<4; nt++)
            mma16816(acc[mt][nt], af[mt][0],af[mt][1],af[mt][2],af[mt][3],
                     bf[nt][0], bf[nt][1]);
      }
    }

    /* epilogue */
#pragma unroll
    for (int mt=0; mt<4; mt++){
#pragma unroll
      for (int nt=0; nt<4; nt++){
        int m = m0 + wm + mt*16 + (lane>>2);
        int n = n0 + wn + nt*8 + (lane&3)*2;
        if (MODE == 0){
          *(__half2*)(g_Pext + (size_t)m*LDC + n)     = __floats2half2_rn(acc[mt][nt][0], acc[mt][nt][1]);
          *(__half2*)(g_Pext + (size_t)(m+8)*LDC + n) = __floats2half2_rn(acc[mt][nt][2], acc[mt][nt][3]);
        } else {
          *(float2*)(Cout + (size_t)m*LDC + n)     = make_float2(acc[mt][nt][0], acc[mt][nt][1]);
          *(float2*)(Cout + (size_t)(m+8)*LDC + n) = make_float2(acc[mt][nt][2], acc[mt][nt][3]);
        }
      }
      if (MODE == 0 && n0 < 1024){
        /* per-warp-column LN partials: slice (n0+wn)>>5 unique -> no race */
        float s0=0.f, q0=0.f, s1=0.f, q1=0.f;
#pragma unroll
        for (int nt=0; nt<4; nt++){
#pragma unroll
          for (int e=0; e<2; e++){
            float v0 = acc[mt][nt][e];   s0 += v0; q0 = fmaf(v0, v0, q0);
            float v1 = acc[mt][nt][2+e]; s1 += v1; q1 = fmaf(v1, v1, q1);
          }
        }
#pragma unroll
        for (int o=1; o<=2; o<<=1){
          s0 += __shfl_xor_sync(0xffffffffu, s0, o);
          q0 += __shfl_xor_sync(0xffffffffu, q0, o);
          s1 += __shfl_xor_sync(0xffffffffu, s1, o);
          q1 += __shfl_xor_sync(0xffffffffu, q1, o);
        }
        if ((lane & 3) == 0){
          int m  = m0 + wm + mt*16 + (lane>>2);
          int sl = (n0 + wn) >> 5;
          g_psum[sl][m]   = s0; g_psq[sl][m]   = q0;
          g_psum[sl][m+8] = s1; g_psq[sl][m+8] = q1;
        }
      }
    }
  }
}

/* ------------------------------ scan stage ------------------------------
   Affine decomposition: h_i = h_i^0 + cumA_i * s0 (cumA per head, running
   prod of a — the chunk-carry keeps the slope a pure product).
   scanA: gates + local scan from 0 -> h^0 to g_h16, cumA, (A,B) per segment.
   compose: s0 per segment (+ exact fp32 h_final).
   fixup: h16 += cumA * s0  (L2-resident RMW).                            */
__device__ __forceinline__ void scan_gates(int m0, float* s_a, float* s_c,
                                           float* s_mu, float* s_rr){
  int tid = threadIdx.x;
  if (tid < 128){
    int m = m0 + tid;
    float sm = 0.f, sq = 0.f;
#pragma unroll
    for (int sl = 0; sl < 32; sl++){ sm += g_psum[sl][m]; sq += g_psq[sl][m]; }
    float mu  = sm*(1.f/1024.f);
    float var = sq*(1.f/1024.f) - mu*mu;
    s_mu[tid] = mu;
    s_rr[tid] = rsqrtf(var + 1e-5f);
  }
  __syncthreads();
  int r = tid >> 3, j = tid & 7;
  int m = m0 + r;
  float mu = s_mu[r], rr = s_rr[r];
  const __half* pr = g_Pext + (size_t)m*NEXT_;
#pragma unroll
  for (int q = 0; q < 2; q++){
    int h = j*2 + q;
    float xga = __half2float(pr[1024 + h]);
    float xgb = __half2float(pr[1040 + h]);
    float xf  = __half2float(pr[1056 + h]);
    float ga = rr*(xga - mu*g_s[h])      + g_c1[h];
    float gb = rr*(xgb - mu*g_s[16 + h]) + g_c1[16 + h];
    float al = 1.f/(1.f + expf(-ga));
    float be = 1.f/(1.f + expf(-gb));
    float f  = 1.f/(1.f + expf(-xf));
    s_a[r*16 + h] = f*g_eig[h]*al;
    s_c[r*16 + h] = (1.f - f)*be;
  }
}

__global__ void k_scanA(const float* __restrict__ gamma, const float* __restrict__ beta){
  __shared__ float s_a[128*16], s_c[128*16], s_mu[128], s_rr[128];
  int c = threadIdx.x, seg = blockIdx.x, b = blockIdx.y;
  int m0 = b*S_ + seg*TSEG_;
  scan_gates(m0, s_a, s_c, s_mu, s_rr);
  __syncthreads();
  int hd = c >> 6;
  float gam = gamma[c], bet = beta[c];
  float Aacc = 1.f, s = 0.f, hout = 0.f;
  for (int ch = 0; ch < TSEG_/CS_; ch++){
#pragma unroll
    for (int i = 0; i < CS_; i++){
      int lr = ch*CS_ + i;
      float p  = __half2float(g_Pext[(size_t)(m0+lr)*NEXT_ + c]);
      float xp = (p - s_mu[lr])*s_rr[lr]*gam + bet;
      float a  = s_a[lr*16 + hd];
      float bi = s_c[lr*16 + hd]*xp;
      Aacc *= a;
      s = a*(s + bi);
      hout = fmaf(1.f - a, bi, s);
      g_h16[(size_t)(m0+lr)*HID_ + c] = __float2half(hout);
      if ((c & 63) == 0) g_cumA[(size_t)(m0+lr)*NH_ + hd] = Aacc;
    }
    s = hout;                                 /* chunk-boundary carry */
  }
  int o = (b*NSEG_ + seg)*HID_ + c;
  g_Aseg[o] = Aacc; g_Bseg[o] = hout;
}

__global__ void k_compose(const float* __restrict__ h0, float* __restrict__ hfin){
  int c = threadIdx.x, b = blockIdx.x;
  float h = h0[b*HID_ + c];
  for (int s = 0; s < NSEG_; s++){
    int o = (b*NSEG_ + s)*HID_ + c;
    g_S0[o] = h;
    h = fmaf(g_Aseg[o], h, g_Bseg[o]);
  }
  hfin[b*HID_ + c] = h;                       /* exact fp32 final state */
}

__global__ void k_fixup(){
  int c = threadIdx.x;
  int q = blockIdx.x, seg = blockIdx.y, b = blockIdx.z;
  int m0 = b*S_ + seg*TSEG_ + q*32;
  float s0 = g_S0[(b*NSEG_ + seg)*HID_ + c];
  int hd = c >> 6;
#pragma unroll 4
  for (int i = 0; i < 32; i++){
    size_t idx = (size_t)(m0 + i)*HID_ + c;
    float ca = g_cumA[(size_t)(m0 + i)*NH_ + hd];
    g_h16[idx] = __float2half(__half2float(g_h16[idx]) + ca*s0);
  }
}

/* --------------------------------- launch --------------------------------- */
extern "C" void kernel_launch(void* const* d_in, const int* in_sizes, int n_in,
                              void* d_out, int out_size){
  const float* x     = (const float*)d_in[0];
  const float* h0    = (const float*)d_in[1];
  const float* W_in  = (const float*)d_in[2];
  const float* gamma = (const float*)d_in[3];
  const float* beta  = (const float*)d_in[4];
  const float* Wg    = (const float*)d_in[5];
  const float* bg    = (const float*)d_in[6];
  const float* Wf    = (const float*)d_in[7];
  const float* Wout  = (const float*)d_in[8];
  const float* eraw  = (const float*)d_in[9];
  float* out = (float*)d_out;

  cudaFuncSetAttribute(k_gemm<0>, cudaFuncAttributeMaxDynamicSharedMemorySize, GSM_TOTAL_);
  cudaFuncSetAttribute(k_gemm<1>, cudaFuncAttributeMaxDynamicSharedMemorySize, GSM_TOTAL_);

  /* 7 launches; slot 4 (profiled) = k_scanA */
  k_prep_all <<<NB_CONV_ + NB_GEMMG_ + 1, 256>>>(x, W_in, Wg, bg, gamma, beta, eraw);
  k_fill_Bmat<<<FILLB_BLKS_ + FILLW_BLKS_, 256>>>(W_in, Wf, Wout);
  k_gemm<0>  <<<GEMM_GRID_, 512, GSM_TOTAL_>>>(nullptr);
  k_scanA    <<<dim3(NSEG_, B_), 1024>>>(gamma, beta);
  k_compose  <<<B_, 1024>>>(h0, out + OUT_OFF_);
  k_fixup    <<<dim3(4, NSEG_, B_), 1024>>>();
  k_gemm<1>  <<<GEMM_GRID_, 512, GSM_TOTAL_>>>(out);
}

// round 14
// speedup vs baseline: 1.1680x; 1.1680x over previous
#include <cuda_runtime.h>
#include <cuda_fp16.h>
#include <stdint.h>

#define B_    4
#define S_    4096
#define HID_  1024
#define NH_   16
#define M_    (B_*S_)      /* 16384 rows */
#define K_    1024
#define NEXT_ 1152         /* GEMM1 N: 1024 P + 32 gates + 16 forget + 80 pad */
#define NSEG_ 32
#define TSEG_ 128
#define CS_   16
#define OUT_OFF_ ((size_t)M_*HID_)

/* ------------------- device scratch (static, no allocs) ------------------- */
__device__ __half g_xh   [(size_t)M_*K_];
__device__ __half g_Bmat [(size_t)NEXT_*K_];
__device__ __half g_Wouth[(size_t)HID_*K_];
__device__ __half g_Pext [(size_t)M_*NEXT_];
__device__ float  g_psum[32][M_], g_psq[32][M_];   /* per-32col-slice LN partials */
__device__ float  g_s[32], g_c1[32], g_eig[16];
__device__ float  g_Gpart[8*32*1024];
__device__ float  g_Aseg[B_*NSEG_*HID_], g_Bseg[B_*NSEG_*HID_];
__device__ float  g_ga[(size_t)M_*NH_], g_gc[(size_t)M_*NH_];  /* saved gates */
__device__ float  g_gmu[M_], g_grr[M_];
__device__ __half g_h16 [(size_t)M_*HID_];

/* ============ prep_all: conv x -> fp16 | gemmG partials | s/c1/eig ============ */
#define NB_CONV_  (M_*K_/4/256)     /* 16384 */
#define NB_GEMMG_ 256               /* 32 gates x 8 k-slices */
__global__ void k_prep_all(const float* __restrict__ x,
                           const float* __restrict__ W_in,
                           const float* __restrict__ Wg,  const float* __restrict__ bg,
                           const float* __restrict__ gamma, const float* __restrict__ beta,
                           const float* __restrict__ eraw){
  const int bid = blockIdx.x, tid = threadIdx.x;
  if (bid < NB_CONV_){
    size_t i = (size_t)bid*256 + tid;
    float4 v = ((const float4*)x)[i];
    __half2* d = (__half2*)g_xh;
    d[2*i]   = __floats2half2_rn(v.x, v.y);
    d[2*i+1] = __floats2half2_rn(v.z, v.w);
    return;
  }
  int rem = bid - NB_CONV_;
  if (rem < NB_GEMMG_){
    __shared__ float wgg[128];
    const int g = rem & 31, ky = rem >> 5, k0 = ky*128;
    if (tid < 128) wgg[tid] = gamma[k0 + tid]*Wg[g*1024 + k0 + tid];
    __syncthreads();
    float acc[4] = {0.f,0.f,0.f,0.f};
    for (int k = 0; k < 128; k++){
      float w = wgg[k];
      const float* r = W_in + (size_t)(k0 + k)*1024 + tid;
#pragma unroll
      for (int j = 0; j < 4; j++) acc[j] = fmaf(w, r[j*256], acc[j]);
    }
#pragma unroll
    for (int j = 0; j < 4; j++) g_Gpart[(ky*32 + g)*1024 + tid + j*256] = acc[j];
    return;
  }
  int w = tid >> 5, lane = tid & 31;
  for (int g = w; g < 32; g += 8){
    float ss = 0.f, cc = 0.f;
    for (int k = lane; k < 1024; k += 32){
      float wv = Wg[g*1024 + k];
      ss += gamma[k]*wv;
      cc += beta[k]*wv;
    }
    for (int o = 16; o; o >>= 1){
      ss += __shfl_xor_sync(0xffffffffu, ss, o);
      cc += __shfl_xor_sync(0xffffffffu, cc, o);
    }
    if (lane == 0){ g_s[g] = ss; g_c1[g] = cc + bg[g]; }
  }
  if (tid < 16) g_eig[tid] = tanhf(eraw[tid]);
}

/* --- fill Bmat rows [W_in; G; Wf; 0] AND convert Wout (merged kernel) --- */
#define FILLB_BLKS_ (NEXT_*K_/256)          /* 4608 */
#define FILLW_BLKS_ (HID_*K_/256)           /* 4096 */
__global__ void k_fill_Bmat(const float* __restrict__ W_in, const float* __restrict__ Wf,
                            const float* __restrict__ Wout){
  int bid = blockIdx.x;
  if (bid < FILLB_BLKS_){
    int idx = bid*256 + threadIdx.x;
    int row = idx >> 10, col = idx & 1023;
    float v;
    if (row < 1024)       v = W_in[idx];
    else if (row < 1056){
      int g = row - 1024;
      v = 0.f;
#pragma unroll
      for (int ky = 0; ky < 8; ky++) v += g_Gpart[(ky*32 + g)*1024 + col];
    }
    else if (row < 1072)  v = Wf[(row-1056)*1024 + col];
    else                  v = 0.f;
    g_Bmat[idx] = __float2half(v);
  } else {
    int idx = (bid - FILLB_BLKS_)*256 + threadIdx.x;
    g_Wouth[idx] = __float2half(Wout[idx]);
  }
}

/* ------------------------------ fp16 GEMM (mma.sync) ------------------------------
   Persistent CTAs. 256x128 CTA tile, 512 threads (16 warps, 4x4), 64x32 warp
   tile, k-tile 64, 4-stage cp.async pipeline. Swizzle chunk' = chunk ^ (row&7).
   MODE 0 epilogue emits per-32col-slice LN partials (unique writer).       */
__device__ __forceinline__ void ldm_x4(unsigned addr, unsigned &r0, unsigned &r1, unsigned &r2, unsigned &r3){
  asm volatile("ldmatrix.sync.aligned.m8n8.x4.shared.b16 {%0,%1,%2,%3}, [%4];"
               : "=r"(r0),"=r"(r1),"=r"(r2),"=r"(r3) : "r"(addr));
}
__device__ __forceinline__ void mma16816(float c[4], unsigned a0, unsigned a1, unsigned a2, unsigned a3,
                                         unsigned b0, unsigned b1){
  asm volatile("mma.sync.aligned.m16n8k16.row.col.f32.f16.f16.f32 "
               "{%0,%1,%2,%3},{%4,%5,%6,%7},{%8,%9},{%0,%1,%2,%3};"
               : "+f"(c[0]),"+f"(c[1]),"+f"(c[2]),"+f"(c[3])
               : "r"(a0),"r"(a1),"r"(a2),"r"(a3),"r"(b0),"r"(b1));
}

#define GASTAGE_ 32768
#define GBSTAGE_ 16384
#define GB_OFF_  (4*GASTAGE_)
#define GSM_TOTAL_ (4*GASTAGE_ + 4*GBSTAGE_)   /* 192 KB */
#define GEMM_GRID_ 152

template<int MODE>   /* 0: P_ext(fp16) = x_h @ Bmat^T   1: out(fp32) = h16 @ Wout^T */
__global__ void __launch_bounds__(512,1) k_gemm(float* __restrict__ Cout){
  constexpr int LDC = (MODE==0) ? NEXT_ : HID_;
  constexpr int NTN = (MODE==0) ? 9 : 8;
  constexpr int NT  = (M_/256)*NTN;
  const __half* __restrict__ A  = (MODE==0) ? g_xh   : g_h16;
  const __half* __restrict__ Bm = (MODE==0) ? g_Bmat : g_Wouth;

  extern __shared__ __align__(128) char smem[];
  const unsigned sbase = (unsigned)__cvta_generic_to_shared(smem);

  const int tid = threadIdx.x;
  const int lane = tid & 31, warp = tid >> 5;
  const int wm = (warp & 3)*64, wn = (warp >> 2)*32;
  const int unit = tid & 7;
  const int rb   = tid >> 3;

  for (int t = blockIdx.x; t < NT; t += GEMM_GRID_){
    const int m0 = (t / NTN)*256, n0 = (t % NTN)*128;

    __syncthreads();

    float acc[4][4][4];
#pragma unroll
    for (int i=0;i<4;i++)
#pragma unroll
      for (int j=0;j<4;j++)
#pragma unroll
        for (int k=0;k<4;k++) acc[i][j][k]=0.f;

    auto load_tiles = [&](int stage, int kt){
      const int kb = kt*64 + unit*8;
      const unsigned abase = sbase + stage*GASTAGE_;
      const unsigned bbase = sbase + GB_OFF_ + stage*GBSTAGE_;
#pragma unroll
      for (int i=0;i<4;i++){
        int r = rb + i*64;
        unsigned d = abase + r*128 + ((unit ^ (r&7))*16);
        asm volatile("cp.async.cg.shared.global [%0], [%1], 16;"
                     :: "r"(d), "l"(A + (size_t)(m0+r)*K_ + kb));
      }
#pragma unroll
      for (int i=0;i<2;i++){
        int r = rb + i*64;
        unsigned d = bbase + r*128 + ((unit ^ (r&7))*16);
        asm volatile("cp.async.cg.shared.global [%0], [%1], 16;"
                     :: "r"(d), "l"(Bm + (size_t)(n0+r)*K_ + kb));
      }
      asm volatile("cp.async.commit_group;");
    };

    load_tiles(0, 0);
    load_tiles(1, 1);
    load_tiles(2, 2);
    const int NK = K_/64;
    for (int kt = 0; kt < NK; kt++){
      asm volatile("cp.async.wait_group 2;\n");
      __syncthreads();
      if (kt+3 < NK) load_tiles((kt+3)&3, kt+3);
      else           asm volatile("cp.async.commit_group;\n");
      const int stage = kt & 3;
      const unsigned abase = sbase + stage*GASTAGE_;
      const unsigned bbase = sbase + GB_OFF_ + stage*GBSTAGE_;
#pragma unroll
      for (int ks = 0; ks < 4; ks++){
        const int kc  = ks*16 + ((lane&16)?8:0);
        const int kcb = ks*16 + ((lane&8)?8:0);
        unsigned af[4][4];
#pragma unroll
        for (int mt=0; mt<4; mt++){
          int row = wm + mt*16 + (lane&15);
          ldm_x4(abase + row*128 + (((kc>>3) ^ (row&7))*16),
                 af[mt][0],af[mt][1],af[mt][2],af[mt][3]);
        }
        unsigned bf[4][2];
#pragma unroll
        for (int np=0; np<2; np++){
          int row = wn + np*16 + (lane&7) + ((lane&16)?8:0);
          unsigned t0,t1,t2,t3;
          ldm_x4(bbase + row*128 + (((kcb>>3) ^ (row&7))*16), t0,t1,t2,t3);
          bf[np*2][0]=t0; bf[np*2][1]=t1; bf[np*2+1][0]=t2; bf[np*2+1][1]=t3;
        }
#pragma unroll
        for (int mt=0; mt<4; mt++)
#pragma unroll
          for (int nt=0; nt<4; nt++)
            mma16816(acc[mt][nt], af[mt][0],af[mt][1],af[mt][2],af[mt][3],
                     bf[nt][0], bf[nt][1]);
      }
    }

    /* epilogue */
#pragma unroll
    for (int mt=0; mt<4; mt++){
#pragma unroll
      for (int nt=0; nt<4; nt++){
        int m = m0 + wm + mt*16 + (lane>>2);
        int n = n0 + wn + nt*8 + (lane&3)*2;
        if (MODE == 0){
          *(__half2*)(g_Pext + (size_t)m*LDC + n)     = __floats2half2_rn(acc[mt][nt][0], acc[mt][nt][1]);
          *(__half2*)(g_Pext + (size_t)(m+8)*LDC + n) = __floats2half2_rn(acc[mt][nt][2], acc[mt][nt][3]);
        } else {
          *(float2*)(Cout + (size_t)m*LDC + n)     = make_float2(acc[mt][nt][0], acc[mt][nt][1]);
          *(float2*)(Cout + (size_t)(m+8)*LDC + n) = make_float2(acc[mt][nt][2], acc[mt][nt][3]);
        }
      }
      if (MODE == 0 && n0 < 1024){
        float s0=0.f, q0=0.f, s1=0.f, q1=0.f;
#pragma unroll
        for (int nt=0; nt<4; nt++){
#pragma unroll
          for (int e=0; e<2; e++){
            float v0 = acc[mt][nt][e];   s0 += v0; q0 = fmaf(v0, v0, q0);
            float v1 = acc[mt][nt][2+e]; s1 += v1; q1 = fmaf(v1, v1, q1);
          }
        }
#pragma unroll
        for (int o=1; o<=2; o<<=1){
          s0 += __shfl_xor_sync(0xffffffffu, s0, o);
          q0 += __shfl_xor_sync(0xffffffffu, q0, o);
          s1 += __shfl_xor_sync(0xffffffffu, s1, o);
          q1 += __shfl_xor_sync(0xffffffffu, q1, o);
        }
        if ((lane & 3) == 0){
          int m  = m0 + wm + mt*16 + (lane>>2);
          int sl = (n0 + wn) >> 5;
          g_psum[sl][m]   = s0; g_psq[sl][m]   = q0;
          g_psum[sl][m+8] = s1; g_psq[sl][m+8] = q1;
        }
      }
    }
  }
}

/* ------------------------------ segmented scan ------------------------------
   scan1: compute gates (save to global) + per-segment (A,B).
   scan3: load saved gates, compose segment-entry state from (A,B) prefix,
          emit h_all (fp16) + h_final. Exact reference chunk semantics:
     s <- a_i*(s + b_i);  h_i = s + (1-a_i)*b_i;  chunk carry = h_15       */
__device__ __forceinline__ void scan_gates_compute(int m0, float* s_a, float* s_c,
                                                   float* s_mu, float* s_rr){
  int tid = threadIdx.x;
  if (tid < 128){
    int m = m0 + tid;
    float sm = 0.f, sq = 0.f;
#pragma unroll
    for (int sl = 0; sl < 32; sl++){ sm += g_psum[sl][m]; sq += g_psq[sl][m]; }
    float mu  = sm*(1.f/1024.f);
    float var = sq*(1.f/1024.f) - mu*mu;
    float rr  = rsqrtf(var + 1e-5f);
    s_mu[tid] = mu;
    s_rr[tid] = rr;
    g_gmu[m] = mu; g_grr[m] = rr;
  }
  __syncthreads();
  int r = tid >> 3, j = tid & 7;
  int m = m0 + r;
  float mu = s_mu[r], rr = s_rr[r];
  const __half* pr = g_Pext + (size_t)m*NEXT_;
#pragma unroll
  for (int q = 0; q < 2; q++){
    int h = j*2 + q;
    float xga = __half2float(pr[1024 + h]);
    float xgb = __half2float(pr[1040 + h]);
    float xf  = __half2float(pr[1056 + h]);
    float ga = rr*(xga - mu*g_s[h])      + g_c1[h];
    float gb = rr*(xgb - mu*g_s[16 + h]) + g_c1[16 + h];
    float al = 1.f/(1.f + expf(-ga));
    float be = 1.f/(1.f + expf(-gb));
    float f  = 1.f/(1.f + expf(-xf));
    float av = f*g_eig[h]*al;
    float cv = (1.f - f)*be;
    s_a[r*16 + h] = av;
    s_c[r*16 + h] = cv;
    g_ga[(size_t)m*NH_ + h] = av;
    g_gc[(size_t)m*NH_ + h] = cv;
  }
}

__device__ __forceinline__ void scan_gates_load(int m0, float* s_a, float* s_c,
                                                float* s_mu, float* s_rr){
  int tid = threadIdx.x;
  if (tid < 128){
    s_mu[tid] = g_gmu[m0 + tid];
    s_rr[tid] = g_grr[m0 + tid];
  }
  s_a[tid]        = g_ga[(size_t)m0*NH_ + tid];
  s_a[tid + 1024] = g_ga[(size_t)m0*NH_ + tid + 1024];
  s_c[tid]        = g_gc[(size_t)m0*NH_ + tid];
  s_c[tid + 1024] = g_gc[(size_t)m0*NH_ + tid + 1024];
}

__global__ void k_scan1(const float* __restrict__ gamma, const float* __restrict__ beta){
  __shared__ float s_a[128*16], s_c[128*16], s_mu[128], s_rr[128];
  int c = threadIdx.x, seg = blockIdx.x, b = blockIdx.y;
  int m0 = b*S_ + seg*TSEG_;
  scan_gates_compute(m0, s_a, s_c, s_mu, s_rr);
  __syncthreads();
  int hd = c >> 6;
  float gam = gamma[c], bet = beta[c];
  float Aacc = 1.f, s = 0.f;
  for (int ch = 0; ch < TSEG_/CS_; ch++){
#pragma unroll
    for (int i = 0; i < CS_; i++){
      int lr = ch*CS_ + i;
      float p  = __half2float(g_Pext[(size_t)(m0+lr)*NEXT_ + c]);
      float xp = (p - s_mu[lr])*s_rr[lr]*gam + bet;
      float a  = s_a[lr*16 + hd];
      float bi = s_c[lr*16 + hd]*xp;
      Aacc *= a;
      s = a*(s + bi);
      if (i == CS_-1) s = fmaf(1.f - a, bi, s);
    }
  }
  int o = (b*NSEG_ + seg)*HID_ + c;
  g_Aseg[o] = Aacc; g_Bseg[o] = s;
}

__global__ void k_scan3(const float* __restrict__ gamma, const float* __restrict__ beta,
                        const float* __restrict__ h0, float* __restrict__ hfin){
  __shared__ float s_a[128*16], s_c[128*16], s_mu[128], s_rr[128];
  int c = threadIdx.x, seg = blockIdx.x, b = blockIdx.y;
  int m0 = b*S_ + seg*TSEG_;
  scan_gates_load(m0, s_a, s_c, s_mu, s_rr);
  __syncthreads();
  int hd = c >> 6;
  float gam = gamma[c], bet = beta[c];
  float s = h0[b*HID_ + c];
  for (int s2 = 0; s2 < seg; s2++){
    int o = (b*NSEG_ + s2)*HID_ + c;
    s = fmaf(g_Aseg[o], s, g_Bseg[o]);
  }
  float hout = s;
  for (int ch = 0; ch < TSEG_/CS_; ch++){
#pragma unroll
    for (int i = 0; i < CS_; i++){
      int lr = ch*CS_ + i;
      float p  = __half2float(g_Pext[(size_t)(m0+lr)*NEXT_ + c]);
      float xp = (p - s_mu[lr])*s_rr[lr]*gam + bet;
      float a  = s_a[lr*16 + hd];
      float bi = s_c[lr*16 + hd]*xp;
      s = a*(s + bi);
      hout = fmaf(1.f - a, bi, s);
      g_h16[(size_t)(m0+lr)*HID_ + c] = __float2half(hout);
    }
    s = hout;
  }
  if (seg == NSEG_-1) hfin[b*HID_ + c] = hout;
}

/* --------------------------------- launch --------------------------------- */
extern "C" void kernel_launch(void* const* d_in, const int* in_sizes, int n_in,
                              void* d_out, int out_size){
  const float* x     = (const float*)d_in[0];
  const float* h0    = (const float*)d_in[1];
  const float* W_in  = (const float*)d_in[2];
  const float* gamma = (const float*)d_in[3];
  const float* beta  = (const float*)d_in[4];
  const float* Wg    = (const float*)d_in[5];
  const float* bg    = (const float*)d_in[6];
  const float* Wf    = (const float*)d_in[7];
  const float* Wout  = (const float*)d_in[8];
  const float* eraw  = (const float*)d_in[9];
  float* out = (float*)d_out;

  cudaFuncSetAttribute(k_gemm<0>, cudaFuncAttributeMaxDynamicSharedMemorySize, GSM_TOTAL_);
  cudaFuncSetAttribute(k_gemm<1>, cudaFuncAttributeMaxDynamicSharedMemorySize, GSM_TOTAL_);

  /* 6 launches; slot 4 (profiled) = k_scan1 */
  k_prep_all <<<NB_CONV_ + NB_GEMMG_ + 1, 256>>>(x, W_in, Wg, bg, gamma, beta, eraw);
  k_fill_Bmat<<<FILLB_BLKS_ + FILLW_BLKS_, 256>>>(W_in, Wf, Wout);
  k_gemm<0>  <<<GEMM_GRID_, 512, GSM_TOTAL_>>>(nullptr);
  k_scan1    <<<dim3(NSEG_, B_), 1024>>>(gamma, beta);
  k_scan3    <<<dim3(NSEG_, B_), 1024>>>(gamma, beta, h0, out + OUT_OFF_);
  k_gemm<1>  <<<GEMM_GRID_, 512, GSM_TOTAL_>>>(out);
}

// round 15
// speedup vs baseline: 1.1835x; 1.0133x over previous
#include <cuda_runtime.h>
#include <cuda_fp16.h>
#include <stdint.h>

#define B_    4
#define S_    4096
#define HID_  1024
#define NH_   16
#define M_    (B_*S_)      /* 16384 rows */
#define K_    1024
#define NEXT_ 1152         /* GEMM1 N: 1024 P + 32 gates + 16 forget + 80 pad */
#define NSEG_ 64
#define TSEG_ 64
#define CS_   16
#define OUT_OFF_ ((size_t)M_*HID_)

/* ------------------- device scratch (static, no allocs) ------------------- */
__device__ __half g_xh   [(size_t)M_*K_];
__device__ __half g_Bmat [(size_t)NEXT_*K_];
__device__ __half g_Wouth[(size_t)HID_*K_];
__device__ __half g_Pext [(size_t)M_*NEXT_];
__device__ float  g_psum[32][M_], g_psq[32][M_];   /* per-32col-slice LN partials */
__device__ float  g_s[32], g_c1[32], g_eig[16];
__device__ float  g_Gpart[8*32*1024];
__device__ float  g_Aseg[B_*NSEG_*HID_], g_Bseg[B_*NSEG_*HID_];
__device__ float  g_ga[(size_t)M_*NH_], g_gc[(size_t)M_*NH_];  /* saved gates */
__device__ float  g_gmu[M_], g_grr[M_];
__device__ __half g_h16 [(size_t)M_*HID_];

/* ============ prep_all: conv x -> fp16 | gemmG partials | s/c1/eig ============ */
#define NB_CONV_  (M_*K_/4/256)     /* 16384 */
#define NB_GEMMG_ 256               /* 32 gates x 8 k-slices */
__global__ void k_prep_all(const float* __restrict__ x,
                           const float* __restrict__ W_in,
                           const float* __restrict__ Wg,  const float* __restrict__ bg,
                           const float* __restrict__ gamma, const float* __restrict__ beta,
                           const float* __restrict__ eraw){
  const int bid = blockIdx.x, tid = threadIdx.x;
  if (bid < NB_CONV_){
    size_t i = (size_t)bid*256 + tid;
    float4 v = ((const float4*)x)[i];
    __half2* d = (__half2*)g_xh;
    d[2*i]   = __floats2half2_rn(v.x, v.y);
    d[2*i+1] = __floats2half2_rn(v.z, v.w);
    return;
  }
  int rem = bid - NB_CONV_;
  if (rem < NB_GEMMG_){
    __shared__ float wgg[128];
    const int g = rem & 31, ky = rem >> 5, k0 = ky*128;
    if (tid < 128) wgg[tid] = gamma[k0 + tid]*Wg[g*1024 + k0 + tid];
    __syncthreads();
    float acc[4] = {0.f,0.f,0.f,0.f};
    for (int k = 0; k < 128; k++){
      float w = wgg[k];
      const float* r = W_in + (size_t)(k0 + k)*1024 + tid;
#pragma unroll
      for (int j = 0; j < 4; j++) acc[j] = fmaf(w, r[j*256], acc[j]);
    }
#pragma unroll
    for (int j = 0; j < 4; j++) g_Gpart[(ky*32 + g)*1024 + tid + j*256] = acc[j];
    return;
  }
  int w = tid >> 5, lane = tid & 31;
  for (int g = w; g < 32; g += 8){
    float ss = 0.f, cc = 0.f;
    for (int k = lane; k < 1024; k += 32){
      float wv = Wg[g*1024 + k];
      ss += gamma[k]*wv;
      cc += beta[k]*wv;
    }
    for (int o = 16; o; o >>= 1){
      ss += __shfl_xor_sync(0xffffffffu, ss, o);
      cc += __shfl_xor_sync(0xffffffffu, cc, o);
    }
    if (lane == 0){ g_s[g] = ss; g_c1[g] = cc + bg[g]; }
  }
  if (tid < 16) g_eig[tid] = tanhf(eraw[tid]);
}

/* --- fill Bmat rows [W_in; G; Wf; 0] AND convert Wout (merged kernel) --- */
#define FILLB_BLKS_ (NEXT_*K_/256)          /* 4608 */
#define FILLW_BLKS_ (HID_*K_/256)           /* 4096 */
__global__ void k_fill_Bmat(const float* __restrict__ W_in, const float* __restrict__ Wf,
                            const float* __restrict__ Wout){
  int bid = blockIdx.x;
  if (bid < FILLB_BLKS_){
    int idx = bid*256 + threadIdx.x;
    int row = idx >> 10, col = idx & 1023;
    float v;
    if (row < 1024)       v = W_in[idx];
    else if (row < 1056){
      int g = row - 1024;
      v = 0.f;
#pragma unroll
      for (int ky = 0; ky < 8; ky++) v += g_Gpart[(ky*32 + g)*1024 + col];
    }
    else if (row < 1072)  v = Wf[(row-1056)*1024 + col];
    else                  v = 0.f;
    g_Bmat[idx] = __float2half(v);
  } else {
    int idx = (bid - FILLB_BLKS_)*256 + threadIdx.x;
    g_Wouth[idx] = __float2half(Wout[idx]);
  }
}

/* ------------------------------ fp16 GEMM (mma.sync) ------------------------------
   Persistent CTAs. 256x128 CTA tile, 512 threads (16 warps, 4x4), 64x32 warp
   tile, k-tile 64, 4-stage cp.async pipeline. Swizzle chunk' = chunk ^ (row&7).
   MODE 0 epilogue emits per-32col-slice LN partials (unique writer).       */
__device__ __forceinline__ void ldm_x4(unsigned addr, unsigned &r0, unsigned &r1, unsigned &r2, unsigned &r3){
  asm volatile("ldmatrix.sync.aligned.m8n8.x4.shared.b16 {%0,%1,%2,%3}, [%4];"
               : "=r"(r0),"=r"(r1),"=r"(r2),"=r"(r3) : "r"(addr));
}
__device__ __forceinline__ void mma16816(float c[4], unsigned a0, unsigned a1, unsigned a2, unsigned a3,
                                         unsigned b0, unsigned b1){
  asm volatile("mma.sync.aligned.m16n8k16.row.col.f32.f16.f16.f32 "
               "{%0,%1,%2,%3},{%4,%5,%6,%7},{%8,%9},{%0,%1,%2,%3};"
               : "+f"(c[0]),"+f"(c[1]),"+f"(c[2]),"+f"(c[3])
               : "r"(a0),"r"(a1),"r"(a2),"r"(a3),"r"(b0),"r"(b1));
}

#define GASTAGE_ 32768
#define GBSTAGE_ 16384
#define GB_OFF_  (4*GASTAGE_)
#define GSM_TOTAL_ (4*GASTAGE_ + 4*GBSTAGE_)   /* 192 KB */
#define GEMM_GRID_ 152

template<int MODE>   /* 0: P_ext(fp16) = x_h @ Bmat^T   1: out(fp32) = h16 @ Wout^T */
__global__ void __launch_bounds__(512,1) k_gemm(float* __restrict__ Cout){
  constexpr int LDC = (MODE==0) ? NEXT_ : HID_;
  constexpr int NTN = (MODE==0) ? 9 : 8;
  constexpr int NT  = (M_/256)*NTN;
  const __half* __restrict__ A  = (MODE==0) ? g_xh   : g_h16;
  const __half* __restrict__ Bm = (MODE==0) ? g_Bmat : g_Wouth;

  extern __shared__ __align__(128) char smem[];
  const unsigned sbase = (unsigned)__cvta_generic_to_shared(smem);

  const int tid = threadIdx.x;
  const int lane = tid & 31, warp = tid >> 5;
  const int wm = (warp & 3)*64, wn = (warp >> 2)*32;
  const int unit = tid & 7;
  const int rb   = tid >> 3;

  for (int t = blockIdx.x; t < NT; t += GEMM_GRID_){
    const int m0 = (t / NTN)*256, n0 = (t % NTN)*128;

    __syncthreads();

    float acc[4][4][4];
#pragma unroll
    for (int i=0;i<4;i++)
#pragma unroll
      for (int j=0;j<4;j++)
#pragma unroll
        for (int k=0;k<4;k++) acc[i][j][k]=0.f;

    auto load_tiles = [&](int stage, int kt){
      const int kb = kt*64 + unit*8;
      const unsigned abase = sbase + stage*GASTAGE_;
      const unsigned bbase = sbase + GB_OFF_ + stage*GBSTAGE_;
#pragma unroll
      for (int i=0;i<4;i++){
        int r = rb + i*64;
        unsigned d = abase + r*128 + ((unit ^ (r&7))*16);
        asm volatile("cp.async.cg.shared.global [%0], [%1], 16;"
                     :: "r"(d), "l"(A + (size_t)(m0+r)*K_ + kb));
      }
#pragma unroll
      for (int i=0;i<2;i++){
        int r = rb + i*64;
        unsigned d = bbase + r*128 + ((unit ^ (r&7))*16);
        asm volatile("cp.async.cg.shared.global [%0], [%1], 16;"
                     :: "r"(d), "l"(Bm + (size_t)(n0+r)*K_ + kb));
      }
      asm volatile("cp.async.commit_group;");
    };

    load_tiles(0, 0);
    load_tiles(1, 1);
    load_tiles(2, 2);
    const int NK = K_/64;
    for (int kt = 0; kt < NK; kt++){
      asm volatile("cp.async.wait_group 2;\n");
      __syncthreads();
      if (kt+3 < NK) load_tiles((kt+3)&3, kt+3);
      else           asm volatile("cp.async.commit_group;\n");
      const int stage = kt & 3;
      const unsigned abase = sbase + stage*GASTAGE_;
      const unsigned bbase = sbase + GB_OFF_ + stage*GBSTAGE_;
#pragma unroll
      for (int ks = 0; ks < 4; ks++){
        const int kc  = ks*16 + ((lane&16)?8:0);
        const int kcb = ks*16 + ((lane&8)?8:0);
        unsigned af[4][4];
#pragma unroll
        for (int mt=0; mt<4; mt++){
          int row = wm + mt*16 + (lane&15);
          ldm_x4(abase + row*128 + (((kc>>3) ^ (row&7))*16),
                 af[mt][0],af[mt][1],af[mt][2],af[mt][3]);
        }
        unsigned bf[4][2];
#pragma unroll
        for (int np=0; np<2; np++){
          int row = wn + np*16 + (lane&7) + ((lane&16)?8:0);
          unsigned t0,t1,t2,t3;
          ldm_x4(bbase + row*128 + (((kcb>>3) ^ (row&7))*16), t0,t1,t2,t3);
          bf[np*2][0]=t0; bf[np*2][1]=t1; bf[np*2+1][0]=t2; bf[np*2+1][1]=t3;
        }
#pragma unroll
        for (int mt=0; mt<4; mt++)
#pragma unroll
          for (int nt=0; nt<4; nt++)
            mma16816(acc[mt][nt], af[mt][0],af[mt][1],af[mt][2],af[mt][3],
                     bf[nt][0], bf[nt][1]);
      }
    }

    /* epilogue */
#pragma unroll
    for (int mt=0; mt<4; mt++){
#pragma unroll
      for (int nt=0; nt<4; nt++){
        int m = m0 + wm + mt*16 + (lane>>2);
        int n = n0 + wn + nt*8 + (lane&3)*2;
        if (MODE == 0){
          *(__half2*)(g_Pext + (size_t)m*LDC + n)     = __floats2half2_rn(acc[mt][nt][0], acc[mt][nt][1]);
          *(__half2*)(g_Pext + (size_t)(m+8)*LDC + n) = __floats2half2_rn(acc[mt][nt][2], acc[mt][nt][3]);
        } else {
          *(float2*)(Cout + (size_t)m*LDC + n)     = make_float2(acc[mt][nt][0], acc[mt][nt][1]);
          *(float2*)(Cout + (size_t)(m+8)*LDC + n) = make_float2(acc[mt][nt][2], acc[mt][nt][3]);
        }
      }
      if (MODE == 0 && n0 < 1024){
        float s0=0.f, q0=0.f, s1=0.f, q1=0.f;
#pragma unroll
        for (int nt=0; nt<4; nt++){
#pragma unroll
          for (int e=0; e<2; e++){
            float v0 = acc[mt][nt][e];   s0 += v0; q0 = fmaf(v0, v0, q0);
            float v1 = acc[mt][nt][2+e]; s1 += v1; q1 = fmaf(v1, v1, q1);
          }
        }
#pragma unroll
        for (int o=1; o<=2; o<<=1){
          s0 += __shfl_xor_sync(0xffffffffu, s0, o);
          q0 += __shfl_xor_sync(0xffffffffu, q0, o);
          s1 += __shfl_xor_sync(0xffffffffu, s1, o);
          q1 += __shfl_xor_sync(0xffffffffu, q1, o);
        }
        if ((lane & 3) == 0){
          int m  = m0 + wm + mt*16 + (lane>>2);
          int sl = (n0 + wn) >> 5;
          g_psum[sl][m]   = s0; g_psq[sl][m]   = q0;
          g_psum[sl][m+8] = s1; g_psq[sl][m+8] = q1;
        }
      }
    }
  }
}

/* ------------------------------ segmented scan ------------------------------
   TSEG=64 rows per block, grid (64 segs x 4 batch) = 256 blocks.
   scan1: compute gates (save) + per-segment (A,B).
   scan3: load gates, compose segment-entry state from (A,B) prefix,
          emit h_all (fp16) + h_final. Exact reference chunk semantics:
     s <- a_i*(s + b_i);  h_i = s + (1-a_i)*b_i;  chunk carry = h_15       */
__device__ __forceinline__ void scan_gates_compute(int m0, float* s_a, float* s_c,
                                                   float* s_mu, float* s_rr){
  int tid = threadIdx.x;
  if (tid < TSEG_){
    int m = m0 + tid;
    float sm = 0.f, sq = 0.f;
#pragma unroll
    for (int sl = 0; sl < 32; sl++){ sm += g_psum[sl][m]; sq += g_psq[sl][m]; }
    float mu  = sm*(1.f/1024.f);
    float var = sq*(1.f/1024.f) - mu*mu;
    float rr  = rsqrtf(var + 1e-5f);
    s_mu[tid] = mu;
    s_rr[tid] = rr;
    g_gmu[m] = mu; g_grr[m] = rr;
  }
  __syncthreads();
  int r = tid >> 4, h = tid & 15;            /* 64 rows x 16 heads */
  int m = m0 + r;
  float mu = s_mu[r], rr = s_rr[r];
  const __half* pr = g_Pext + (size_t)m*NEXT_;
  float xga = __half2float(pr[1024 + h]);
  float xgb = __half2float(pr[1040 + h]);
  float xf  = __half2float(pr[1056 + h]);
  float ga = rr*(xga - mu*g_s[h])      + g_c1[h];
  float gb = rr*(xgb - mu*g_s[16 + h]) + g_c1[16 + h];
  float al = 1.f/(1.f + expf(-ga));
  float be = 1.f/(1.f + expf(-gb));
  float f  = 1.f/(1.f + expf(-xf));
  float av = f*g_eig[h]*al;
  float cv = (1.f - f)*be;
  s_a[r*16 + h] = av;
  s_c[r*16 + h] = cv;
  g_ga[(size_t)m*NH_ + h] = av;
  g_gc[(size_t)m*NH_ + h] = cv;
}

__device__ __forceinline__ void scan_gates_load(int m0, float* s_a, float* s_c,
                                                float* s_mu, float* s_rr){
  int tid = threadIdx.x;
  if (tid < TSEG_){
    s_mu[tid] = g_gmu[m0 + tid];
    s_rr[tid] = g_grr[m0 + tid];
  }
  s_a[tid] = g_ga[(size_t)m0*NH_ + tid];     /* 64*16 = 1024 entries */
  s_c[tid] = g_gc[(size_t)m0*NH_ + tid];
}

__global__ void k_scan1(const float* __restrict__ gamma, const float* __restrict__ beta){
  __shared__ float s_a[TSEG_*16], s_c[TSEG_*16], s_mu[TSEG_], s_rr[TSEG_];
  int c = threadIdx.x, seg = blockIdx.x, b = blockIdx.y;
  int m0 = b*S_ + seg*TSEG_;
  scan_gates_compute(m0, s_a, s_c, s_mu, s_rr);
  __syncthreads();
  int hd = c >> 6;
  float gam = gamma[c], bet = beta[c];
  float Aacc = 1.f, s = 0.f;
  for (int ch = 0; ch < TSEG_/CS_; ch++){
#pragma unroll
    for (int i = 0; i < CS_; i++){
      int lr = ch*CS_ + i;
      float p  = __half2float(g_Pext[(size_t)(m0+lr)*NEXT_ + c]);
      float xp = (p - s_mu[lr])*s_rr[lr]*gam + bet;
      float a  = s_a[lr*16 + hd];
      float bi = s_c[lr*16 + hd]*xp;
      Aacc *= a;
      s = a*(s + bi);
      if (i == CS_-1) s = fmaf(1.f - a, bi, s);
    }
  }
  int o = (b*NSEG_ + seg)*HID_ + c;
  g_Aseg[o] = Aacc; g_Bseg[o] = s;
}

__global__ void k_scan3(const float* __restrict__ gamma, const float* __restrict__ beta,
                        const float* __restrict__ h0, float* __restrict__ hfin){
  __shared__ float s_a[TSEG_*16], s_c[TSEG_*16], s_mu[TSEG_], s_rr[TSEG_];
  int c = threadIdx.x, seg = blockIdx.x, b = blockIdx.y;
  int m0 = b*S_ + seg*TSEG_;
  scan_gates_load(m0, s_a, s_c, s_mu, s_rr);
  __syncthreads();
  int hd = c >> 6;
  float gam = gamma[c], bet = beta[c];
  float s = h0[b*HID_ + c];
  for (int s2 = 0; s2 < seg; s2++){
    int o = (b*NSEG_ + s2)*HID_ + c;
    s = fmaf(g_Aseg[o], s, g_Bseg[o]);
  }
  float hout = s;
  for (int ch = 0; ch < TSEG_/CS_; ch++){
#pragma unroll
    for (int i = 0; i < CS_; i++){
      int lr = ch*CS_ + i;
      float p  = __half2float(g_Pext[(size_t)(m0+lr)*NEXT_ + c]);
      float xp = (p - s_mu[lr])*s_rr[lr]*gam + bet;
      float a  = s_a[lr*16 + hd];
      float bi = s_c[lr*16 + hd]*xp;
      s = a*(s + bi);
      hout = fmaf(1.f - a, bi, s);
      g_h16[(size_t)(m0+lr)*HID_ + c] = __float2half(hout);
    }
    s = hout;
  }
  if (seg == NSEG_-1) hfin[b*HID_ + c] = hout;
}

/* --------------------------------- launch --------------------------------- */
extern "C" void kernel_launch(void* const* d_in, const int* in_sizes, int n_in,
                              void* d_out, int out_size){
  const float* x     = (const float*)d_in[0];
  const float* h0    = (const float*)d_in[1];
  const float* W_in  = (const float*)d_in[2];
  const float* gamma = (const float*)d_in[3];
  const float* beta  = (const float*)d_in[4];
  const float* Wg    = (const float*)d_in[5];
  const float* bg    = (const float*)d_in[6];
  const float* Wf    = (const float*)d_in[7];
  const float* Wout  = (const float*)d_in[8];
  const float* eraw  = (const float*)d_in[9];
  float* out = (float*)d_out;

  cudaFuncSetAttribute(k_gemm<0>, cudaFuncAttributeMaxDynamicSharedMemorySize, GSM_TOTAL_);
  cudaFuncSetAttribute(k_gemm<1>, cudaFuncAttributeMaxDynamicSharedMemorySize, GSM_TOTAL_);

  /* 6 launches; slot 4 (profiled) = k_scan1 */
  k_prep_all <<<NB_CONV_ + NB_GEMMG_ + 1, 256>>>(x, W_in, Wg, bg, gamma, beta, eraw);
  k_fill_Bmat<<<FILLB_BLKS_ + FILLW_BLKS_, 256>>>(W_in, Wf, Wout);
  k_gemm<0>  <<<GEMM_GRID_, 512, GSM_TOTAL_>>>(nullptr);
  k_scan1    <<<dim3(NSEG_, B_), 1024>>>(gamma, beta);
  k_scan3    <<<dim3(NSEG_, B_), 1024>>>(gamma, beta, h0, out + OUT_OFF_);
  k_gemm<1>  <<<GEMM_GRID_, 512, GSM_TOTAL_>>>(out);
}

// round 16
// speedup vs baseline: 1.2041x; 1.0174x over previous
#include <cuda_runtime.h>
#include <cuda_fp16.h>
#include <stdint.h>

#define B_    4
#define S_    4096
#define HID_  1024
#define NH_   16
#define M_    (B_*S_)      /* 16384 rows */
#define K_    1024
#define NEXT_ 1152         /* GEMM1 N: 1024 P + 32 gates + 16 forget + 80 pad */
#define NSEG_ 64
#define TSEG_ 64
#define CS_   16
#define OUT_OFF_ ((size_t)M_*HID_)

/* ------------------- device scratch (static, no allocs) ------------------- */
__device__ __half g_xh   [(size_t)M_*K_];
__device__ __half g_Bmat [(size_t)NEXT_*K_];
__device__ __half g_Wouth[(size_t)HID_*K_];
__device__ __half g_Pext [(size_t)M_*NEXT_];
__device__ float  g_psum[32][M_], g_psq[32][M_];   /* per-32col-slice LN partials */
__device__ float  g_s[32], g_c1[32], g_eig[16];
__device__ float  g_Gpart[8*32*1024];
__device__ float  g_Aseg[B_*NSEG_*HID_], g_Bseg[B_*NSEG_*HID_];
__device__ float  g_ga[(size_t)M_*NH_], g_gc[(size_t)M_*NH_];  /* saved gates */
__device__ float  g_gmu[M_], g_grr[M_];
__device__ __half g_h16 [(size_t)M_*HID_];

/* ============ prep_all: conv x -> fp16 | gemmG partials | s/c1/eig ============ */
#define NB_CONV_  (M_*K_/4/256)     /* 16384 */
#define NB_GEMMG_ 256               /* 32 gates x 8 k-slices */
__global__ void k_prep_all(const float* __restrict__ x,
                           const float* __restrict__ W_in,
                           const float* __restrict__ Wg,  const float* __restrict__ bg,
                           const float* __restrict__ gamma, const float* __restrict__ beta,
                           const float* __restrict__ eraw){
  const int bid = blockIdx.x, tid = threadIdx.x;
  if (bid < NB_CONV_){
    size_t i = (size_t)bid*256 + tid;
    float4 v = ((const float4*)x)[i];
    __half2* d = (__half2*)g_xh;
    d[2*i]   = __floats2half2_rn(v.x, v.y);
    d[2*i+1] = __floats2half2_rn(v.z, v.w);
    return;
  }
  int rem = bid - NB_CONV_;
  if (rem < NB_GEMMG_){
    __shared__ float wgg[128];
    const int g = rem & 31, ky = rem >> 5, k0 = ky*128;
    if (tid < 128) wgg[tid] = gamma[k0 + tid]*Wg[g*1024 + k0 + tid];
    __syncthreads();
    float acc[4] = {0.f,0.f,0.f,0.f};
    for (int k = 0; k < 128; k++){
      float w = wgg[k];
      const float* r = W_in + (size_t)(k0 + k)*1024 + tid;
#pragma unroll
      for (int j = 0; j < 4; j++) acc[j] = fmaf(w, r[j*256], acc[j]);
    }
#pragma unroll
    for (int j = 0; j < 4; j++) g_Gpart[(ky*32 + g)*1024 + tid + j*256] = acc[j];
    return;
  }
  int w = tid >> 5, lane = tid & 31;
  for (int g = w; g < 32; g += 8){
    float ss = 0.f, cc = 0.f;
    for (int k = lane; k < 1024; k += 32){
      float wv = Wg[g*1024 + k];
      ss += gamma[k]*wv;
      cc += beta[k]*wv;
    }
    for (int o = 16; o; o >>= 1){
      ss += __shfl_xor_sync(0xffffffffu, ss, o);
      cc += __shfl_xor_sync(0xffffffffu, cc, o);
    }
    if (lane == 0){ g_s[g] = ss; g_c1[g] = cc + bg[g]; }
  }
  if (tid < 16) g_eig[tid] = tanhf(eraw[tid]);
}

/* --- fill Bmat rows [W_in; G; Wf; 0] AND convert Wout (merged kernel) --- */
#define FILLB_BLKS_ (NEXT_*K_/256)          /* 4608 */
#define FILLW_BLKS_ (HID_*K_/256)           /* 4096 */
__global__ void k_fill_Bmat(const float* __restrict__ W_in, const float* __restrict__ Wf,
                            const float* __restrict__ Wout){
  int bid = blockIdx.x;
  if (bid < FILLB_BLKS_){
    int idx = bid*256 + threadIdx.x;
    int row = idx >> 10, col = idx & 1023;
    float v;
    if (row < 1024)       v = W_in[idx];
    else if (row < 1056){
      int g = row - 1024;
      v = 0.f;
#pragma unroll
      for (int ky = 0; ky < 8; ky++) v += g_Gpart[(ky*32 + g)*1024 + col];
    }
    else if (row < 1072)  v = Wf[(row-1056)*1024 + col];
    else                  v = 0.f;
    g_Bmat[idx] = __float2half(v);
  } else {
    int idx = (bid - FILLB_BLKS_)*256 + threadIdx.x;
    g_Wouth[idx] = __float2half(Wout[idx]);
  }
}

/* ------------------------------ fp16 GEMM (mma.sync) ------------------------------
   Persistent CTAs. 256x128 CTA tile, 512 threads (16 warps, 4x4), 64x32 warp
   tile, k-tile 64, 4-stage cp.async pipeline. Swizzle chunk' = chunk ^ (row&7).
   MODE 0 epilogue emits per-32col-slice LN partials (unique writer).       */
__device__ __forceinline__ void ldm_x4(unsigned addr, unsigned &r0, unsigned &r1, unsigned &r2, unsigned &r3){
  asm volatile("ldmatrix.sync.aligned.m8n8.x4.shared.b16 {%0,%1,%2,%3}, [%4];"
               : "=r"(r0),"=r"(r1),"=r"(r2),"=r"(r3) : "r"(addr));
}
__device__ __forceinline__ void mma16816(float c[4], unsigned a0, unsigned a1, unsigned a2, unsigned a3,
                                         unsigned b0, unsigned b1){
  asm volatile("mma.sync.aligned.m16n8k16.row.col.f32.f16.f16.f32 "
               "{%0,%1,%2,%3},{%4,%5,%6,%7},{%8,%9},{%0,%1,%2,%3};"
               : "+f"(c[0]),"+f"(c[1]),"+f"(c[2]),"+f"(c[3])
               : "r"(a0),"r"(a1),"r"(a2),"r"(a3),"r"(b0),"r"(b1));
}

#define GASTAGE_ 32768
#define GBSTAGE_ 16384
#define GB_OFF_  (4*GASTAGE_)
#define GSM_TOTAL_ (4*GASTAGE_ + 4*GBSTAGE_)   /* 192 KB */
#define GEMM_GRID_ 152

template<int MODE>   /* 0: P_ext(fp16) = x_h @ Bmat^T   1: out(fp32) = h16 @ Wout^T */
__global__ void __launch_bounds__(512,1) k_gemm(float* __restrict__ Cout){
  constexpr int LDC = (MODE==0) ? NEXT_ : HID_;
  constexpr int NTN = (MODE==0) ? 9 : 8;
  constexpr int NT  = (M_/256)*NTN;
  const __half* __restrict__ A  = (MODE==0) ? g_xh   : g_h16;
  const __half* __restrict__ Bm = (MODE==0) ? g_Bmat : g_Wouth;

  extern __shared__ __align__(128) char smem[];
  const unsigned sbase = (unsigned)__cvta_generic_to_shared(smem);

  const int tid = threadIdx.x;
  const int lane = tid & 31, warp = tid >> 5;
  const int wm = (warp & 3)*64, wn = (warp >> 2)*32;
  const int unit = tid & 7;
  const int rb   = tid >> 3;

  for (int t = blockIdx.x; t < NT; t += GEMM_GRID_){
    const int m0 = (t / NTN)*256, n0 = (t % NTN)*128;

    __syncthreads();

    float acc[4][4][4];
#pragma unroll
    for (int i=0;i<4;i++)
#pragma unroll
      for (int j=0;j<4;j++)
#pragma unroll
        for (int k=0;k<4;k++) acc[i][j][k]=0.f;

    auto load_tiles = [&](int stage, int kt){
      const int kb = kt*64 + unit*8;
      const unsigned abase = sbase + stage*GASTAGE_;
      const unsigned bbase = sbase + GB_OFF_ + stage*GBSTAGE_;
#pragma unroll
      for (int i=0;i<4;i++){
        int r = rb + i*64;
        unsigned d = abase + r*128 + ((unit ^ (r&7))*16);
        asm volatile("cp.async.cg.shared.global [%0], [%1], 16;"
                     :: "r"(d), "l"(A + (size_t)(m0+r)*K_ + kb));
      }
#pragma unroll
      for (int i=0;i<2;i++){
        int r = rb + i*64;
        unsigned d = bbase + r*128 + ((unit ^ (r&7))*16);
        asm volatile("cp.async.cg.shared.global [%0], [%1], 16;"
                     :: "r"(d), "l"(Bm + (size_t)(n0+r)*K_ + kb));
      }
      asm volatile("cp.async.commit_group;");
    };

    load_tiles(0, 0);
    load_tiles(1, 1);
    load_tiles(2, 2);
    const int NK = K_/64;
    for (int kt = 0; kt < NK; kt++){
      asm volatile("cp.async.wait_group 2;\n");
      __syncthreads();
      if (kt+3 < NK) load_tiles((kt+3)&3, kt+3);
      else           asm volatile("cp.async.commit_group;\n");
      const int stage = kt & 3;
      const unsigned abase = sbase + stage*GASTAGE_;
      const unsigned bbase = sbase + GB_OFF_ + stage*GBSTAGE_;
#pragma unroll
      for (int ks = 0; ks < 4; ks++){
        const int kc  = ks*16 + ((lane&16)?8:0);
        const int kcb = ks*16 + ((lane&8)?8:0);
        unsigned af[4][4];
#pragma unroll
        for (int mt=0; mt<4; mt++){
          int row = wm + mt*16 + (lane&15);
          ldm_x4(abase + row*128 + (((kc>>3) ^ (row&7))*16),
                 af[mt][0],af[mt][1],af[mt][2],af[mt][3]);
        }
        unsigned bf[4][2];
#pragma unroll
        for (int np=0; np<2; np++){
          int row = wn + np*16 + (lane&7) + ((lane&16)?8:0);
          unsigned t0,t1,t2,t3;
          ldm_x4(bbase + row*128 + (((kcb>>3) ^ (row&7))*16), t0,t1,t2,t3);
          bf[np*2][0]=t0; bf[np*2][1]=t1; bf[np*2+1][0]=t2; bf[np*2+1][1]=t3;
        }
#pragma unroll
        for (int mt=0; mt<4; mt++)
#pragma unroll
          for (int nt=0; nt<4; nt++)
            mma16816(acc[mt][nt], af[mt][0],af[mt][1],af[mt][2],af[mt][3],
                     bf[nt][0], bf[nt][1]);
      }
    }

    /* epilogue */
#pragma unroll
    for (int mt=0; mt<4; mt++){
#pragma unroll
      for (int nt=0; nt<4; nt++){
        int m = m0 + wm + mt*16 + (lane>>2);
        int n = n0 + wn + nt*8 + (lane&3)*2;
        if (MODE == 0){
          *(__half2*)(g_Pext + (size_t)m*LDC + n)     = __floats2half2_rn(acc[mt][nt][0], acc[mt][nt][1]);
          *(__half2*)(g_Pext + (size_t)(m+8)*LDC + n) = __floats2half2_rn(acc[mt][nt][2], acc[mt][nt][3]);
        } else {
          *(float2*)(Cout + (size_t)m*LDC + n)     = make_float2(acc[mt][nt][0], acc[mt][nt][1]);
          *(float2*)(Cout + (size_t)(m+8)*LDC + n) = make_float2(acc[mt][nt][2], acc[mt][nt][3]);
        }
      }
      if (MODE == 0 && n0 < 1024){
        float s0=0.f, q0=0.f, s1=0.f, q1=0.f;
#pragma unroll
        for (int nt=0; nt<4; nt++){
#pragma unroll
          for (int e=0; e<2; e++){
            float v0 = acc[mt][nt][e];   s0 += v0; q0 = fmaf(v0, v0, q0);
            float v1 = acc[mt][nt][2+e]; s1 += v1; q1 = fmaf(v1, v1, q1);
          }
        }
#pragma unroll
        for (int o=1; o<=2; o<<=1){
          s0 += __shfl_xor_sync(0xffffffffu, s0, o);
          q0 += __shfl_xor_sync(0xffffffffu, q0, o);
          s1 += __shfl_xor_sync(0xffffffffu, s1, o);
          q1 += __shfl_xor_sync(0xffffffffu, q1, o);
        }
        if ((lane & 3) == 0){
          int m  = m0 + wm + mt*16 + (lane>>2);
          int sl = (n0 + wn) >> 5;
          g_psum[sl][m]   = s0; g_psq[sl][m]   = q0;
          g_psum[sl][m+8] = s1; g_psq[sl][m+8] = q1;
        }
      }
    }
  }
}

/* ------------------------------ segmented scan ------------------------------
   512 threads/block, 2 adjacent channels per thread (same head): packed
   float2 smem operands, half2 Pext loads, dual recurrence chains (ILP 2).
   Exact reference chunk semantics:
     s <- a_i*(s + b_i);  h_i = s + (1-a_i)*b_i;  chunk carry = h_15       */
__device__ __forceinline__ void scan_gates_compute(int m0, float2* s_mr, float2* s_ac){
  int tid = threadIdx.x;
  if (tid < TSEG_){
    int m = m0 + tid;
    float sm = 0.f, sq = 0.f;
#pragma unroll
    for (int sl = 0; sl < 32; sl++){ sm += g_psum[sl][m]; sq += g_psq[sl][m]; }
    float mu  = sm*(1.f/1024.f);
    float var = sq*(1.f/1024.f) - mu*mu;
    float rr  = rsqrtf(var + 1e-5f);
    s_mr[tid] = make_float2(mu, rr);
    g_gmu[m] = mu; g_grr[m] = rr;
  }
  __syncthreads();
#pragma unroll
  for (int it = threadIdx.x; it < TSEG_*16; it += 512){
    int r = it >> 4, h = it & 15;
    int m = m0 + r;
    float2 mr = s_mr[r];
    const __half* pr = g_Pext + (size_t)m*NEXT_;
    float xga = __half2float(pr[1024 + h]);
    float xgb = __half2float(pr[1040 + h]);
    float xf  = __half2float(pr[1056 + h]);
    float ga = mr.y*(xga - mr.x*g_s[h])      + g_c1[h];
    float gb = mr.y*(xgb - mr.x*g_s[16 + h]) + g_c1[16 + h];
    float al = 1.f/(1.f + expf(-ga));
    float be = 1.f/(1.f + expf(-gb));
    float f  = 1.f/(1.f + expf(-xf));
    float av = f*g_eig[h]*al;
    float cv = (1.f - f)*be;
    s_ac[it] = make_float2(av, cv);
    g_ga[(size_t)m*NH_ + h] = av;
    g_gc[(size_t)m*NH_ + h] = cv;
  }
}

__device__ __forceinline__ void scan_gates_load(int m0, float2* s_mr, float2* s_ac){
  int tid = threadIdx.x;
  if (tid < TSEG_) s_mr[tid] = make_float2(g_gmu[m0 + tid], g_grr[m0 + tid]);
#pragma unroll
  for (int it = tid; it < TSEG_*16; it += 512)
    s_ac[it] = make_float2(g_ga[(size_t)m0*NH_ + it], g_gc[(size_t)m0*NH_ + it]);
}

__global__ void __launch_bounds__(512) k_scan1(const float* __restrict__ gamma,
                                               const float* __restrict__ beta){
  __shared__ float2 s_mr[TSEG_];
  __shared__ float2 s_ac[TSEG_*16];
  int tid = threadIdx.x, seg = blockIdx.x, b = blockIdx.y;
  int m0 = b*S_ + seg*TSEG_;
  scan_gates_compute(m0, s_mr, s_ac);
  __syncthreads();
  int c0 = tid*2;
  int hd = c0 >> 6;
  float gam0 = gamma[c0], gam1 = gamma[c0+1];
  float bet0 = beta[c0],  bet1 = beta[c0+1];
  float Aacc = 1.f, sA = 0.f, sB = 0.f;
  for (int ch = 0; ch < TSEG_/CS_; ch++){
#pragma unroll
    for (int i = 0; i < CS_; i++){
      int lr = ch*CS_ + i;
      float2 mr = s_mr[lr];
      float2 ac = s_ac[lr*16 + hd];
      float2 p  = __half22float2(*(const __half2*)(g_Pext + (size_t)(m0+lr)*NEXT_ + c0));
      float xp0 = (p.x - mr.x)*(mr.y*gam0) + bet0;
      float xp1 = (p.y - mr.x)*(mr.y*gam1) + bet1;
      float bi0 = ac.y*xp0, bi1 = ac.y*xp1;
      Aacc *= ac.x;
      sA = ac.x*(sA + bi0);
      sB = ac.x*(sB + bi1);
      if (i == CS_-1){
        sA = fmaf(1.f - ac.x, bi0, sA);
        sB = fmaf(1.f - ac.x, bi1, sB);
      }
    }
  }
  int o = (b*NSEG_ + seg)*HID_ + c0;
  *(float2*)&g_Aseg[o] = make_float2(Aacc, Aacc);
  *(float2*)&g_Bseg[o] = make_float2(sA, sB);
}

__global__ void __launch_bounds__(512) k_scan3(const float* __restrict__ gamma,
                                               const float* __restrict__ beta,
                                               const float* __restrict__ h0,
                                               float* __restrict__ hfin){
  __shared__ float2 s_mr[TSEG_];
  __shared__ float2 s_ac[TSEG_*16];
  int tid = threadIdx.x, seg = blockIdx.x, b = blockIdx.y;
  int m0 = b*S_ + seg*TSEG_;
  scan_gates_load(m0, s_mr, s_ac);
  __syncthreads();
  int c0 = tid*2;
  int hd = c0 >> 6;
  float gam0 = gamma[c0], gam1 = gamma[c0+1];
  float bet0 = beta[c0],  bet1 = beta[c0+1];
  float sA = h0[b*HID_ + c0], sB = h0[b*HID_ + c0 + 1];
  for (int s2 = 0; s2 < seg; s2++){
    int o = (b*NSEG_ + s2)*HID_ + c0;
    float2 Av = *(const float2*)&g_Aseg[o];
    float2 Bv = *(const float2*)&g_Bseg[o];
    sA = fmaf(Av.x, sA, Bv.x);
    sB = fmaf(Av.y, sB, Bv.y);
  }
  float hA = sA, hB = sB;
  for (int ch = 0; ch < TSEG_/CS_; ch++){
#pragma unroll
    for (int i = 0; i < CS_; i++){
      int lr = ch*CS_ + i;
      float2 mr = s_mr[lr];
      float2 ac = s_ac[lr*16 + hd];
      float2 p  = __half22float2(*(const __half2*)(g_Pext + (size_t)(m0+lr)*NEXT_ + c0));
      float xp0 = (p.x - mr.x)*(mr.y*gam0) + bet0;
      float xp1 = (p.y - mr.x)*(mr.y*gam1) + bet1;
      float bi0 = ac.y*xp0, bi1 = ac.y*xp1;
      sA = ac.x*(sA + bi0);
      sB = ac.x*(sB + bi1);
      hA = fmaf(1.f - ac.x, bi0, sA);
      hB = fmaf(1.f - ac.x, bi1, sB);
      *(__half2*)(g_h16 + (size_t)(m0+lr)*HID_ + c0) = __floats2half2_rn(hA, hB);
    }
    sA = hA;
    sB = hB;
  }
  if (seg == NSEG_-1){
    hfin[b*HID_ + c0]     = hA;
    hfin[b*HID_ + c0 + 1] = hB;
  }
}

/* --------------------------------- launch --------------------------------- */
extern "C" void kernel_launch(void* const* d_in, const int* in_sizes, int n_in,
                              void* d_out, int out_size){
  const float* x     = (const float*)d_in[0];
  const float* h0    = (const float*)d_in[1];
  const float* W_in  = (const float*)d_in[2];
  const float* gamma = (const float*)d_in[3];
  const float* beta  = (const float*)d_in[4];
  const float* Wg    = (const float*)d_in[5];
  const float* bg    = (const float*)d_in[6];
  const float* Wf    = (const float*)d_in[7];
  const float* Wout  = (const float*)d_in[8];
  const float* eraw  = (const float*)d_in[9];
  float* out = (float*)d_out;

  cudaFuncSetAttribute(k_gemm<0>, cudaFuncAttributeMaxDynamicSharedMemorySize, GSM_TOTAL_);
  cudaFuncSetAttribute(k_gemm<1>, cudaFuncAttributeMaxDynamicSharedMemorySize, GSM_TOTAL_);

  /* 6 launches; slot 4 (profiled) = k_scan1 */
  k_prep_all <<<NB_CONV_ + NB_GEMMG_ + 1, 256>>>(x, W_in, Wg, bg, gamma, beta, eraw);
  k_fill_Bmat<<<FILLB_BLKS_ + FILLW_BLKS_, 256>>>(W_in, Wf, Wout);
  k_gemm<0>  <<<GEMM_GRID_, 512, GSM_TOTAL_>>>(nullptr);
  k_scan1    <<<dim3(NSEG_, B_), 512>>>(gamma, beta);
  k_scan3    <<<dim3(NSEG_, B_), 512>>>(gamma, beta, h0, out + OUT_OFF_);
  k_gemm<1>  <<<GEMM_GRID_, 512, GSM_TOTAL_>>>(out);
}